// round 9
// baseline (speedup 1.0000x reference)
#include <cuda_runtime.h>
#include <cuda_fp16.h>
#include <cstdint>

// ---------------------------------------------------------------------------
// FanoCoupling via legacy tensor-core mma.sync (HMMA m16n8k16 f16->f32).
//
// Reduction: W = [W1 | W2], each 64x64.  8 unique half-matvecs per row tile:
//   A0=W1 x0, A1=W1 x1, A3=W1 x3, A4=W1 x4, B1=W2 x1, B2=W2 x2, B3=W2 x3, B5=W2 x5
// Combine (g = softmax(gates)):
//   out0=x0, out1=x1, out3=x3
//   out2 = x2 + g0*(A0+B1+b)
//   out4 = x4 + g1*(A0+B3+b)
//   out5 = x5 + g3*(A1+B3+b) + g6*(A4+B2+b)
//   out6 = x6 + g2*(A0+B5+b) + g4*(A4+B1+b) + g5*(A3+B2+b)
//
// CTA = 128 thr, tile = 32 rows.  Warp (of 4) = 16 rows x 32 z, computes all
// 8 results: acc[8][4 ntiles][4].  A,B fragments via ldmatrix from smem with
// 72-half row stride (conflict-free).  W pre-converted to fp16 by pack_w.
// fp32 x pass-through / residual read straight from GMEM (exact).
// ---------------------------------------------------------------------------

#define ROW 448
#define TROWS 32
#define STR 72                          // halves per smem row (144 B, 16B-aligned)
#define XH_COLONY (TROWS * STR)         // 2304 halves per colony tile
#define WH_HALF (64 * STR)              // 4608 halves per W half
#define WH_OFF (6 * XH_COLONY)          // 13824
#define SMEM_HALVES (WH_OFF + 2 * WH_HALF)   // 23040 halves = 46080 B

__device__ __half whg[8192];            // [half h][z][f] fp16 weights

__global__ void pack_w(const float* __restrict__ W) {
    int i = blockIdx.x * 256 + threadIdx.x;
    if (i < 8192) {
        int z = i >> 7, f = i & 127;
        int h = f >> 6, fc = f & 63;
        whg[h * 4096 + z * 64 + fc] = __float2half_rn(W[i]);
    }
}

__device__ __forceinline__ uint32_t s2u(const void* p) {
    uint32_t a;
    asm("{ .reg .u64 t; cvta.to.shared.u64 t, %1; cvt.u32.u64 %0, t; }" : "=r"(a) : "l"(p));
    return a;
}
__device__ __forceinline__ void ldm4(uint32_t* r, uint32_t addr) {
    asm volatile("ldmatrix.sync.aligned.m8n8.x4.shared.b16 {%0,%1,%2,%3}, [%4];"
                 : "=r"(r[0]), "=r"(r[1]), "=r"(r[2]), "=r"(r[3]) : "r"(addr));
}
__device__ __forceinline__ void ldm2(uint32_t* r, uint32_t addr) {
    asm volatile("ldmatrix.sync.aligned.m8n8.x2.shared.b16 {%0,%1}, [%2];"
                 : "=r"(r[0]), "=r"(r[1]) : "r"(addr));
}
__device__ __forceinline__ void mma16816(float* d, const uint32_t* a, const uint32_t* b) {
    asm volatile("mma.sync.aligned.m16n8k16.row.col.f32.f16.f16.f32 "
                 "{%0,%1,%2,%3}, {%4,%5,%6,%7}, {%8,%9}, {%0,%1,%2,%3};"
                 : "+f"(d[0]), "+f"(d[1]), "+f"(d[2]), "+f"(d[3])
                 : "r"(a[0]), "r"(a[1]), "r"(a[2]), "r"(a[3]), "r"(b[0]), "r"(b[1]));
}

__global__ __launch_bounds__(128, 2)
void fano_mma(const float* __restrict__ x, const float* __restrict__ bias,
              const float* __restrict__ gates, float* __restrict__ out, int nrows)
{
    __shared__ __half sh[SMEM_HALVES];
    const int tid = threadIdx.x;
    const long long rowbase = (long long)blockIdx.x * TROWS;
    const int tile_rows = (nrows - rowbase < TROWS) ? (int)(nrows - rowbase) : TROWS;

    // --- stage x (colonies 0..5) fp32 -> fp16, 72-half stride ---------------
    for (int i = tid; i < TROWS * 96; i += 128) {
        int r = i / 96, rem = i % 96, c = rem >> 4, f4 = (rem & 15) * 4;
        float4 v = (r < tile_rows)
            ? *reinterpret_cast<const float4*>(x + (rowbase + r) * (long long)ROW + c * 64 + f4)
            : make_float4(0.f, 0.f, 0.f, 0.f);
        __half2* p = reinterpret_cast<__half2*>(sh + c * XH_COLONY + r * STR + f4);
        p[0] = __floats2half2_rn(v.x, v.y);
        p[1] = __floats2half2_rn(v.z, v.w);
    }
    // --- stage W fp16 (already converted) -----------------------------------
    {
        const uint4* wg = reinterpret_cast<const uint4*>(whg);
        for (int i = tid; i < 1024; i += 128) {
            int hz = i >> 3, f8 = (i & 7) * 8;   // hz = h*64 + z
            *reinterpret_cast<uint4*>(sh + WH_OFF + hz * STR + f8) = wg[i];
        }
    }
    __syncthreads();

    // --- pass-through colonies 0,1,3 (coalesced gmem->gmem) -----------------
    for (int i = tid; i < TROWS * 48; i += 128) {
        int r = i / 48, rem = i % 48, ci = rem / 16, f4 = (rem & 15) * 4;
        int c = (ci < 2) ? ci : 3;
        long long row = rowbase + r;
        if (row < nrows) {
            long long off = row * (long long)ROW + c * 64 + f4;
            *reinterpret_cast<float4*>(out + off) =
                *reinterpret_cast<const float4*>(x + off);
        }
    }

    const int warp = tid >> 5, lane = tid & 31;
    const int rbase = (warp & 1) * 16;      // warp's m-tile
    const int zbase = (warp >> 1) * 32;     // warp's z-half

    const uint32_t sbase = s2u(sh);
    // A ldmatrix lane address: tiles [m0-8,k0-8],[m8-16,k0-8],[m0-8,k8-16],[m8-16,k8-16]
    {
    }
    const int agrp = lane >> 3, alr = lane & 7;
    const int arow = rbase + alr + ((agrp & 1) ? 8 : 0);
    const int akk  = (agrp & 2) ? 8 : 0;
    const uint32_t aoff = sbase + (uint32_t)(arow * STR + akk) * 2;
    // B ldmatrix lane address (x2: lanes 0-15): tile0 k0, tile1 k0+8
    const int blr = lane & 7, bgrp = (lane >> 3) & 1;
    const uint32_t boff = sbase + (uint32_t)(WH_OFF + (zbase + blr) * STR + bgrp * 8) * 2;

    // acc[res][ntile][frag]; res: 0=A0 1=A1 2=A3 3=A4 4=B1 5=B2 6=B3 7=B5
    float acc[8][4][4];
    #pragma unroll
    for (int j = 0; j < 8; j++)
        #pragma unroll
        for (int nt = 0; nt < 4; nt++)
            #pragma unroll
            for (int q = 0; q < 4; q++) acc[j][nt][q] = 0.f;

    #pragma unroll
    for (int ks = 0; ks < 4; ks++) {
        const int k0 = ks * 16;
        uint32_t a[6][4];
        #pragma unroll
        for (int c = 0; c < 6; c++)
            ldm4(a[c], aoff + (uint32_t)(c * XH_COLONY + k0) * 2);
        uint32_t b1[4][2], b2[4][2];
        #pragma unroll
        for (int nt = 0; nt < 4; nt++) {
            ldm2(b1[nt], boff + (uint32_t)(nt * 8 * STR + k0) * 2);
            ldm2(b2[nt], boff + (uint32_t)(WH_HALF + nt * 8 * STR + k0) * 2);
        }
        #pragma unroll
        for (int nt = 0; nt < 4; nt++) {
            mma16816(acc[0][nt], a[0], b1[nt]);   // A0
            mma16816(acc[1][nt], a[1], b1[nt]);   // A1
            mma16816(acc[2][nt], a[3], b1[nt]);   // A3
            mma16816(acc[3][nt], a[4], b1[nt]);   // A4
            mma16816(acc[4][nt], a[1], b2[nt]);   // B1
            mma16816(acc[5][nt], a[2], b2[nt]);   // B2
            mma16816(acc[6][nt], a[3], b2[nt]);   // B3
            mma16816(acc[7][nt], a[5], b2[nt]);   // B5
        }
    }

    // --- gates softmax (tiny, per-thread) -----------------------------------
    float g[7];
    {
        float graw[7];
        #pragma unroll
        for (int i = 0; i < 7; i++) graw[i] = gates[i];
        float m = graw[0];
        #pragma unroll
        for (int i = 1; i < 7; i++) m = fmaxf(m, graw[i]);
        float s = 0.f;
        #pragma unroll
        for (int i = 0; i < 7; i++) { g[i] = expf(graw[i] - m); s += g[i]; }
        float inv = 1.f / s;
        #pragma unroll
        for (int i = 0; i < 7; i++) g[i] *= inv;
    }

    // --- epilogue: D-frag (row=lane/4 [+8], z=2*(lane%4)+{0,1}) -------------
    const int qrow = lane >> 2;
    const int qcol = (lane & 3) * 2;
    #pragma unroll
    for (int nt = 0; nt < 4; nt++) {
        const int z0 = zbase + nt * 8 + qcol;
        const float bz0 = bias[z0], bz1 = bias[z0 + 1];
        #pragma unroll
        for (int hh = 0; hh < 2; hh++) {
            const long long row = rowbase + rbase + qrow + hh * 8;
            if (row >= nrows) continue;
            const float* xr = x + row * (long long)ROW;
            float* orow = out + row * (long long)ROW;
            const int i0 = hh * 2, i1 = hh * 2 + 1;

            float o0, o1;
            // out2 = x2 + g0*(A0+B1+b)
            o0 = xr[2*64 + z0]     + g[0] * (acc[0][nt][i0] + acc[4][nt][i0] + bz0);
            o1 = xr[2*64 + z0 + 1] + g[0] * (acc[0][nt][i1] + acc[4][nt][i1] + bz1);
            *reinterpret_cast<float2*>(orow + 2*64 + z0) = make_float2(o0, o1);
            // out4 = x4 + g1*(A0+B3+b)
            o0 = xr[4*64 + z0]     + g[1] * (acc[0][nt][i0] + acc[6][nt][i0] + bz0);
            o1 = xr[4*64 + z0 + 1] + g[1] * (acc[0][nt][i1] + acc[6][nt][i1] + bz1);
            *reinterpret_cast<float2*>(orow + 4*64 + z0) = make_float2(o0, o1);
            // out5 = x5 + g3*(A1+B3+b) + g6*(A4+B2+b)
            o0 = xr[5*64 + z0]     + g[3] * (acc[1][nt][i0] + acc[6][nt][i0] + bz0)
                                   + g[6] * (acc[3][nt][i0] + acc[5][nt][i0] + bz0);
            o1 = xr[5*64 + z0 + 1] + g[3] * (acc[1][nt][i1] + acc[6][nt][i1] + bz1)
                                   + g[6] * (acc[3][nt][i1] + acc[5][nt][i1] + bz1);
            *reinterpret_cast<float2*>(orow + 5*64 + z0) = make_float2(o0, o1);
            // out6 = x6 + g2*(A0+B5+b) + g4*(A4+B1+b) + g5*(A3+B2+b)
            o0 = xr[6*64 + z0]     + g[2] * (acc[0][nt][i0] + acc[7][nt][i0] + bz0)
                                   + g[4] * (acc[3][nt][i0] + acc[4][nt][i0] + bz0)
                                   + g[5] * (acc[2][nt][i0] + acc[5][nt][i0] + bz0);
            o1 = xr[6*64 + z0 + 1] + g[2] * (acc[0][nt][i1] + acc[7][nt][i1] + bz1)
                                   + g[4] * (acc[3][nt][i1] + acc[4][nt][i1] + bz1)
                                   + g[5] * (acc[2][nt][i1] + acc[5][nt][i1] + bz1);
            *reinterpret_cast<float2*>(orow + 6*64 + z0) = make_float2(o0, o1);
        }
    }
}

extern "C" void kernel_launch(void* const* d_in, const int* in_sizes, int n_in,
                              void* d_out, int out_size) {
    const float* x     = (const float*)d_in[0];   // colony_states [B,7,64]
    const float* W     = (const float*)d_in[1];   // [64,128]
    const float* bias  = (const float*)d_in[2];   // [64]
    const float* gates = (const float*)d_in[3];   // [7]
    float* out = (float*)d_out;

    int nrows = in_sizes[0] / ROW;
    pack_w<<<32, 256>>>(W);
    int ctas = (nrows + TROWS - 1) / TROWS;
    fano_mma<<<ctas, 128>>>(x, bias, gates, out, nrows);
}

// round 10
// speedup vs baseline: 1.6783x; 1.6783x over previous
#include <cuda_runtime.h>
#include <cuda_fp16.h>
#include <cstdint>

// ---------------------------------------------------------------------------
// FanoCoupling: persistent-CTA HMMA pipeline (sm_103a, no tcgen05 on this
// virtual target).  Per 32-row tile: 8 half-matvecs on mma.sync m16n8k16
// (fp16 in, fp32 accum), residual+gating epilogue in fp32.
//
//   W = [W1|W2]; A0=W1x0 A1=W1x1 A3=W1x3 A4=W1x4 B1=W2x1 B2=W2x2 B3=W2x3 B5=W2x5
//   out0=x0 out1=x1 out3=x3
//   out2 = x2 + g0*(A0+B1+b)
//   out4 = x4 + g1*(A0+B3+b)
//   out5 = x5 + g3*(A1+B3+b) + g6*(A4+B2+b)
//   out6 = x6 + g2*(A0+B5+b) + g4*(A4+B1+b) + g5*(A3+B2+b)
//
// Pipeline: double-buffered fp32 tile (cp.async prefetch of tile t+grid while
// processing t), fp32->fp16 convert in smem, MMA, epilogue writes results back
// into the fp32 buffer, single coalesced copy-out of the whole tile.
// ---------------------------------------------------------------------------

#define ROW 448
#define TROWS 32
#define BSTR 452                        // floats per buffered row (pad 16B)
#define BUF_FLOATS (TROWS * BSTR)       // 14464
#define STR 72                          // halves per fp16 row
#define XH_COLONY (TROWS * STR)         // 2304
#define WH_HALF (64 * STR)              // 4608
#define SMEM_BYTES (2 * BUF_FLOATS * 4 + (6 * XH_COLONY + 2 * WH_HALF) * 2) // 161792

__device__ __half whg[8192];            // [h][z][f] fp16 weights

__global__ void pack_w(const float* __restrict__ W) {
    int i = blockIdx.x * 256 + threadIdx.x;
    if (i < 8192) {
        int z = i >> 7, f = i & 127;
        whg[(f >> 6) * 4096 + z * 64 + (f & 63)] = __float2half_rn(W[i]);
    }
}

__device__ __forceinline__ uint32_t s2u(const void* p) {
    uint32_t a;
    asm("{ .reg .u64 t; cvta.to.shared.u64 t, %1; cvt.u32.u64 %0, t; }" : "=r"(a) : "l"(p));
    return a;
}
__device__ __forceinline__ void cpasync16(uint32_t dst, const void* src) {
    asm volatile("cp.async.cg.shared.global [%0], [%1], 16;" :: "r"(dst), "l"(src));
}
#define CP_COMMIT() asm volatile("cp.async.commit_group;" ::: "memory")
#define CP_WAIT(N)  asm volatile("cp.async.wait_group %0;" :: "n"(N) : "memory")

__device__ __forceinline__ void ldm4(uint32_t* r, uint32_t addr) {
    asm volatile("ldmatrix.sync.aligned.m8n8.x4.shared.b16 {%0,%1,%2,%3}, [%4];"
                 : "=r"(r[0]), "=r"(r[1]), "=r"(r[2]), "=r"(r[3]) : "r"(addr));
}
__device__ __forceinline__ void ldm2(uint32_t* r, uint32_t addr) {
    asm volatile("ldmatrix.sync.aligned.m8n8.x2.shared.b16 {%0,%1}, [%2];"
                 : "=r"(r[0]), "=r"(r[1]) : "r"(addr));
}
__device__ __forceinline__ void mma16816(float* d, const uint32_t* a, const uint32_t* b) {
    asm volatile("mma.sync.aligned.m16n8k16.row.col.f32.f16.f16.f32 "
                 "{%0,%1,%2,%3}, {%4,%5,%6,%7}, {%8,%9}, {%0,%1,%2,%3};"
                 : "+f"(d[0]), "+f"(d[1]), "+f"(d[2]), "+f"(d[3])
                 : "r"(a[0]), "r"(a[1]), "r"(a[2]), "r"(a[3]), "r"(b[0]), "r"(b[1]));
}

__global__ __launch_bounds__(256, 1)
void fano_mma(const float* __restrict__ x, const float* __restrict__ bias,
              const float* __restrict__ gates, float* __restrict__ out, int nrows)
{
    extern __shared__ float smf[];
    float*  bufs[2] = { smf, smf + BUF_FLOATS };
    __half* xh = reinterpret_cast<__half*>(smf + 2 * BUF_FLOATS);
    __half* wh = xh + 6 * XH_COLONY;

    const int tid = threadIdx.x;
    const int G = gridDim.x;
    const int NT = (nrows + TROWS - 1) / TROWS;

    // --- stage fp16 W once --------------------------------------------------
    {
        const uint4* wg = reinterpret_cast<const uint4*>(whg);
        for (int i = tid; i < 1024; i += 256) {
            int hz = i >> 3, f8 = (i & 7) * 8;
            *reinterpret_cast<uint4*>(wh + hz * STR + f8) = wg[i];
        }
    }

    // --- gates softmax + hoisted bias ---------------------------------------
    const int warp = tid >> 5, lane = tid & 31;
    const int rbase = (warp & 1) * 16;
    const int zbase = ((warp >> 1) & 3) * 16;
    const int qrow = lane >> 2, qcol = (lane & 3) * 2;

    float g[7];
    {
        float graw[7];
        #pragma unroll
        for (int i = 0; i < 7; i++) graw[i] = gates[i];
        float m = graw[0];
        #pragma unroll
        for (int i = 1; i < 7; i++) m = fmaxf(m, graw[i]);
        float s = 0.f;
        #pragma unroll
        for (int i = 0; i < 7; i++) { g[i] = expf(graw[i] - m); s += g[i]; }
        float inv = 1.f / s;
        #pragma unroll
        for (int i = 0; i < 7; i++) g[i] *= inv;
    }
    float bzv[2][2];
    #pragma unroll
    for (int nt = 0; nt < 2; nt++) {
        bzv[nt][0] = bias[zbase + nt * 8 + qcol];
        bzv[nt][1] = bias[zbase + nt * 8 + qcol + 1];
    }

    // fragment addresses (fixed per thread)
    const int agrp = lane >> 3, alr = lane & 7;
    const int arow = rbase + alr + ((agrp & 1) ? 8 : 0);
    const int akk  = (agrp & 2) ? 8 : 0;
    const uint32_t aoff = s2u(xh) + (uint32_t)(arow * STR + akk) * 2;
    const int blr = lane & 7, bgrp = (lane >> 3) & 1;
    const uint32_t boff = s2u(wh) + (uint32_t)((zbase + blr) * STR + bgrp * 8) * 2;

    const uint32_t bufu[2] = { s2u(bufs[0]), s2u(bufs[1]) };

    // --- prologue: prefetch first tile --------------------------------------
    int t = blockIdx.x;
    if (t < NT) {
        const float* src = x + (long long)t * TROWS * ROW;
        long long rowb = (long long)t * TROWS;
        for (int i = tid; i < TROWS * 112; i += 256) {
            int r = i / 112, ch = i % 112;
            if (rowb + r < nrows)
                cpasync16(bufu[0] + (uint32_t)(r * BSTR + ch * 4) * 4,
                          src + r * ROW + ch * 4);
        }
    }
    CP_COMMIT();

    int pb = 0;
    for (; t < NT; t += G, pb ^= 1) {
        // prefetch next tile into other buffer
        int tn = t + G;
        if (tn < NT) {
            const float* src = x + (long long)tn * TROWS * ROW;
            long long rowb = (long long)tn * TROWS;
            for (int i = tid; i < TROWS * 112; i += 256) {
                int r = i / 112, ch = i % 112;
                if (rowb + r < nrows)
                    cpasync16(bufu[pb ^ 1] + (uint32_t)(r * BSTR + ch * 4) * 4,
                              src + r * ROW + ch * 4);
            }
            CP_COMMIT();
            CP_WAIT(1);
        } else {
            CP_COMMIT();
            CP_WAIT(0);
        }
        __syncthreads();

        float* buf = bufs[pb];

        // --- convert colonies 0..5 fp32 -> fp16 -----------------------------
        for (int i = tid; i < TROWS * 96; i += 256) {
            int r = i / 96, rem = i % 96, c = rem >> 4, f4 = (rem & 15) * 4;
            float4 v = *reinterpret_cast<const float4*>(buf + r * BSTR + c * 64 + f4);
            __half2* p = reinterpret_cast<__half2*>(xh + c * XH_COLONY + r * STR + f4);
            p[0] = __floats2half2_rn(v.x, v.y);
            p[1] = __floats2half2_rn(v.z, v.w);
        }
        __syncthreads();

        // --- MMA: acc[res][nt][frag] ----------------------------------------
        float acc[8][2][4];
        #pragma unroll
        for (int j = 0; j < 8; j++)
            #pragma unroll
            for (int nt = 0; nt < 2; nt++)
                #pragma unroll
                for (int q = 0; q < 4; q++) acc[j][nt][q] = 0.f;

        #pragma unroll
        for (int ks = 0; ks < 4; ks++) {
            const uint32_t k0b = (uint32_t)(ks * 16) * 2;
            uint32_t a[6][4];
            #pragma unroll
            for (int c = 0; c < 6; c++)
                ldm4(a[c], aoff + (uint32_t)(c * XH_COLONY) * 2 + k0b);
            uint32_t b1[2][2], b2[2][2];
            #pragma unroll
            for (int nt = 0; nt < 2; nt++) {
                ldm2(b1[nt], boff + (uint32_t)(nt * 8 * STR) * 2 + k0b);
                ldm2(b2[nt], boff + (uint32_t)(WH_HALF + nt * 8 * STR) * 2 + k0b);
            }
            #pragma unroll
            for (int nt = 0; nt < 2; nt++) {
                mma16816(acc[0][nt], a[0], b1[nt]);   // A0
                mma16816(acc[1][nt], a[1], b1[nt]);   // A1
                mma16816(acc[2][nt], a[3], b1[nt]);   // A3
                mma16816(acc[3][nt], a[4], b1[nt]);   // A4
                mma16816(acc[4][nt], a[1], b2[nt]);   // B1
                mma16816(acc[5][nt], a[2], b2[nt]);   // B2
                mma16816(acc[6][nt], a[3], b2[nt]);   // B3
                mma16816(acc[7][nt], a[5], b2[nt]);   // B5
            }
        }

        // --- epilogue: combine in fp32, write back into buf -----------------
        #pragma unroll
        for (int nt = 0; nt < 2; nt++) {
            const int z0 = zbase + nt * 8 + qcol;
            const float bz0 = bzv[nt][0], bz1 = bzv[nt][1];
            #pragma unroll
            for (int hh = 0; hh < 2; hh++) {
                const int rl = rbase + qrow + hh * 8;
                float* bp = buf + rl * BSTR;
                float2 x2v = *reinterpret_cast<const float2*>(bp + 2 * 64 + z0);
                float2 x4v = *reinterpret_cast<const float2*>(bp + 4 * 64 + z0);
                float2 x5v = *reinterpret_cast<const float2*>(bp + 5 * 64 + z0);
                float2 x6v = *reinterpret_cast<const float2*>(bp + 6 * 64 + z0);
                const int i0 = hh * 2, i1 = hh * 2 + 1;
                float2 o;
                o.x = x2v.x + g[0] * (acc[0][nt][i0] + acc[4][nt][i0] + bz0);
                o.y = x2v.y + g[0] * (acc[0][nt][i1] + acc[4][nt][i1] + bz1);
                *reinterpret_cast<float2*>(bp + 2 * 64 + z0) = o;
                o.x = x4v.x + g[1] * (acc[0][nt][i0] + acc[6][nt][i0] + bz0);
                o.y = x4v.y + g[1] * (acc[0][nt][i1] + acc[6][nt][i1] + bz1);
                *reinterpret_cast<float2*>(bp + 4 * 64 + z0) = o;
                o.x = x5v.x + g[3] * (acc[1][nt][i0] + acc[6][nt][i0] + bz0)
                            + g[6] * (acc[3][nt][i0] + acc[5][nt][i0] + bz0);
                o.y = x5v.y + g[3] * (acc[1][nt][i1] + acc[6][nt][i1] + bz1)
                            + g[6] * (acc[3][nt][i1] + acc[5][nt][i1] + bz1);
                *reinterpret_cast<float2*>(bp + 5 * 64 + z0) = o;
                o.x = x6v.x + g[2] * (acc[0][nt][i0] + acc[7][nt][i0] + bz0)
                            + g[4] * (acc[3][nt][i0] + acc[4][nt][i0] + bz0)
                            + g[5] * (acc[2][nt][i0] + acc[5][nt][i0] + bz0);
                o.y = x6v.y + g[2] * (acc[0][nt][i1] + acc[7][nt][i1] + bz1)
                            + g[4] * (acc[3][nt][i1] + acc[4][nt][i1] + bz1)
                            + g[5] * (acc[2][nt][i1] + acc[5][nt][i1] + bz1);
                *reinterpret_cast<float2*>(bp + 6 * 64 + z0) = o;
            }
        }
        __syncthreads();

        // --- coalesced copy-out of full tile --------------------------------
        {
            long long rowb = (long long)t * TROWS;
            for (int i = tid; i < TROWS * 112; i += 256) {
                int r = i / 112, ch = i % 112;
                long long row = rowb + r;
                if (row < nrows)
                    *reinterpret_cast<float4*>(out + row * (long long)ROW + ch * 4) =
                        *reinterpret_cast<const float4*>(buf + r * BSTR + ch * 4);
            }
        }
        __syncthreads();   // protect buf from next prefetch
    }
}

extern "C" void kernel_launch(void* const* d_in, const int* in_sizes, int n_in,
                              void* d_out, int out_size) {
    const float* x     = (const float*)d_in[0];   // colony_states [B,7,64]
    const float* W     = (const float*)d_in[1];   // [64,128]
    const float* bias  = (const float*)d_in[2];   // [64]
    const float* gates = (const float*)d_in[3];   // [7]
    float* out = (float*)d_out;

    int nrows = in_sizes[0] / ROW;
    pack_w<<<32, 256>>>(W);
    cudaFuncSetAttribute(fano_mma,
                         cudaFuncAttributeMaxDynamicSharedMemorySize, SMEM_BYTES);
    fano_mma<<<148, 256, SMEM_BYTES>>>(x, bias, gates, out, nrows);
}